// round 11
// baseline (speedup 1.0000x reference)
#include <cuda_runtime.h>
#include <math.h>

#define B_ 4
#define N_ 1024
#define H_ 8
#define D_ 256
#define L_ 4
#define DK_ 32
#define NSP_ 512
#define BND (B_*N_*D_)   // 1048576
#define ND  (N_*D_)      // 262144
#define SPLITS 2
#define NROWS (B_*H_*N_) // 32768

typedef unsigned long long u64;

// ---------------- f32x2 packed-math helpers (sm_100+) ----------------
__device__ __forceinline__ u64 pk2(float x, float y) {
    u64 r; asm("mov.b64 %0, {%1, %2};" : "=l"(r) : "f"(x), "f"(y)); return r;
}
__device__ __forceinline__ float2 upk2(u64 a) {
    float2 f; asm("mov.b64 {%0, %1}, %2;" : "=f"(f.x), "=f"(f.y) : "l"(a)); return f;
}
__device__ __forceinline__ u64 fma2_(u64 a, u64 b, u64 c) {
    u64 d; asm("fma.rn.f32x2 %0, %1, %2, %3;" : "=l"(d) : "l"(a), "l"(b), "l"(c)); return d;
}
__device__ __forceinline__ u64 mul2_(u64 a, u64 b) {
    u64 d; asm("mul.rn.f32x2 %0, %1, %2;" : "=l"(d) : "l"(a), "l"(b)); return d;
}

// ---------------- scratch (static device globals; no allocation) ----------------
__device__ float g_h [BND];
__device__ float g_q [BND];
__device__ float g_k [BND];
__device__ float g_v [BND];
__device__ float g_t1[BND];
__device__ float g_t2[BND];
__device__ float g_node[ND];
__device__ float g_bias[H_ * N_ * N_];   // 32MB precomputed bias [H][N][N]
__device__ float g_po[SPLITS * NROWS * DK_];
__device__ float g_pm[SPLITS * NROWS];
__device__ float g_pl[SPLITS * NROWS];

// ---------------- prologue: node-level embeddings ----------------
__global__ void node_vec_kernel(const float* __restrict__ svd_emb,
                                const float* __restrict__ W_svd,
                                const float* __restrict__ b_svd,
                                const float* __restrict__ in_deg_emb,
                                const float* __restrict__ out_deg_emb,
                                const int*   __restrict__ in_degrees,
                                const int*   __restrict__ out_degrees,
                                float* __restrict__ nodevec)
{
    int n = blockIdx.x;
    int d = threadIdx.x;           // 256 threads
    __shared__ float pos[32];
    if (d < 32) {
        float v = svd_emb[n * 32 + d];
        pos[d] = (d < 16) ? v : -v;
    }
    __syncthreads();
    int in_i  = in_degrees[n];
    int out_i = out_degrees[n];
    float acc = b_svd[d] + in_deg_emb[in_i * D_ + d] + out_deg_emb[out_i * D_ + d];
#pragma unroll
    for (int k = 0; k < 32; k++)
        acc += pos[k] * W_svd[k * D_ + d];
    nodevec[n * D_ + d] = acc;
}

__global__ void add_node_kernel(const float* __restrict__ x,
                                const float* __restrict__ nodevec,
                                float* __restrict__ h)
{
    int i = blockIdx.x * blockDim.x + threadIdx.x;
    h[i] = x[i] + nodevec[i & (ND - 1)];
}

// ---------------- precompute attention bias ----------------
__global__ void bias_kernel(const int* __restrict__ spatial_pos,
                            const float* __restrict__ spatial_emb,
                            float* __restrict__ bias)
{
    int i = blockIdx.x * 256 + threadIdx.x;     // over N*N = 1M
    int s = spatial_pos[i];
#pragma unroll
    for (int h = 0; h < H_; h++)
        bias[(size_t)h * (N_ * N_) + i] = spatial_emb[s * H_ + h];
}

// ---------------- GEMM: 128x64 tile, 256 threads, 8m x 4n microtile, f32x2 ----------------
#define GBM 128
#define GBN 64
#define GBK 16
__device__ __forceinline__ void gemm_body(const float* __restrict__ A,
                                          const float* __restrict__ W,
                                          const float* __restrict__ bias,
                                          const float* __restrict__ res,
                                          float* __restrict__ out,
                                          int relu, int bm, int bn)
{
    __shared__ __align__(16) float As[GBK][GBM + 4];  // [16][132]
    __shared__ __align__(16) float Bs[GBK][GBN];      // [16][64]

    int tid = threadIdx.x;            // 256
    int tx = tid & 15;                // n dir: 4 cols
    int ty = tid >> 4;                // m dir: 8 rows (4 f32x2 pairs)

    int ar = tid >> 1;                // A row 0..127
    int ac = (tid & 1) * 8;           // A k-chunk 0 or 8
    int br = tid >> 4;                // B k-row 0..15
    int bc = (tid & 15) * 4;          // B n-chunk

    const float* Ap = A + (size_t)(bm + ar) * 256 + ac;
    const float* Wp = W + (size_t)br * 256 + bn + bc;

    float4 a0 = *reinterpret_cast<const float4*>(Ap);
    float4 a1 = *reinterpret_cast<const float4*>(Ap + 4);
    float4 b0 = *reinterpret_cast<const float4*>(Wp);

    u64 acc2[4][4] = {};   // [m-pair p -> rows ty*8+2p,+2p+1][n j]

#pragma unroll 1
    for (int k0 = 0; k0 < 256; k0 += GBK) {
        As[ac + 0][ar] = a0.x; As[ac + 1][ar] = a0.y;
        As[ac + 2][ar] = a0.z; As[ac + 3][ar] = a0.w;
        As[ac + 4][ar] = a1.x; As[ac + 5][ar] = a1.y;
        As[ac + 6][ar] = a1.z; As[ac + 7][ar] = a1.w;
        *reinterpret_cast<float4*>(&Bs[br][bc]) = b0;
        __syncthreads();
        if (k0 + GBK < 256) {
            a0 = *reinterpret_cast<const float4*>(Ap + k0 + GBK);
            a1 = *reinterpret_cast<const float4*>(Ap + k0 + GBK + 4);
            b0 = *reinterpret_cast<const float4*>(Wp + (size_t)(k0 + GBK) * 256);
        }
#pragma unroll
        for (int kk = 0; kk < GBK; kk++) {
            ulonglong2 aA = *reinterpret_cast<const ulonglong2*>(&As[kk][ty * 8]);
            ulonglong2 aB = *reinterpret_cast<const ulonglong2*>(&As[kk][ty * 8 + 4]);
            float4 b4 = *reinterpret_cast<const float4*>(&Bs[kk][tx * 4]);
            u64 bd[4];
            bd[0] = pk2(b4.x, b4.x); bd[1] = pk2(b4.y, b4.y);
            bd[2] = pk2(b4.z, b4.z); bd[3] = pk2(b4.w, b4.w);
            u64 am[4] = {aA.x, aA.y, aB.x, aB.y};
#pragma unroll
            for (int p = 0; p < 4; p++)
#pragma unroll
                for (int j = 0; j < 4; j++)
                    acc2[p][j] = fma2_(am[p], bd[j], acc2[p][j]);
        }
        __syncthreads();
    }

    int n = bn + tx * 4;
    float4 bb = *reinterpret_cast<const float4*>(bias + n);
#pragma unroll
    for (int p = 0; p < 4; p++) {
#pragma unroll
        for (int half = 0; half < 2; half++) {
            int m = bm + ty * 8 + p * 2 + half;
            float4 vv;
            {
                float2 t0 = upk2(acc2[p][0]);
                float2 t1 = upk2(acc2[p][1]);
                float2 t2 = upk2(acc2[p][2]);
                float2 t3 = upk2(acc2[p][3]);
                if (half) { vv.x = t0.y; vv.y = t1.y; vv.z = t2.y; vv.w = t3.y; }
                else      { vv.x = t0.x; vv.y = t1.x; vv.z = t2.x; vv.w = t3.x; }
            }
            vv.x += bb.x; vv.y += bb.y; vv.z += bb.z; vv.w += bb.w;
            if (res) {
                float4 rr = *reinterpret_cast<const float4*>(res + (size_t)m * 256 + n);
                vv.x += rr.x; vv.y += rr.y; vv.z += rr.z; vv.w += rr.w;
            }
            if (relu) {
                vv.x = fmaxf(vv.x, 0.f); vv.y = fmaxf(vv.y, 0.f);
                vv.z = fmaxf(vv.z, 0.f); vv.w = fmaxf(vv.w, 0.f);
            }
            *reinterpret_cast<float4*>(out + (size_t)m * 256 + n) = vv;
        }
    }
}

__global__ void __launch_bounds__(256)
gemm256_kernel(const float* __restrict__ A, const float* __restrict__ W,
               const float* __restrict__ bias, const float* __restrict__ res,
               float* __restrict__ out, int relu)
{
    gemm_body(A, W, bias, res, out, relu, blockIdx.x * GBM, blockIdx.y * GBN);
}

__global__ void __launch_bounds__(256)
qkv_kernel(const float* __restrict__ A,
           const float* __restrict__ Wq, const float* __restrict__ Wk, const float* __restrict__ Wv,
           const float* __restrict__ bq, const float* __restrict__ bk, const float* __restrict__ bv,
           float* __restrict__ q, float* __restrict__ k, float* __restrict__ v)
{
    const float* W; const float* bias; float* out;
    if (blockIdx.z == 0)      { W = Wq; bias = bq; out = q; }
    else if (blockIdx.z == 1) { W = Wk; bias = bk; out = k; }
    else                      { W = Wv; bias = bv; out = v; }
    gemm_body(A, W, bias, nullptr, out, 0, blockIdx.x * GBM, blockIdx.y * GBN);
}

// ---------------- flash attention, split-KV=2, double-buffered K/V, reg bias ----------------
// grid: (N/128, B*H, SPLITS), block 128. Warp w owns query q0 + w*32 + lane.
// Body identical to R8 best; no launch_bounds occupancy cap (avoid spills).
__global__ void __launch_bounds__(128)
attn_kernel(const float* __restrict__ q,
            const float* __restrict__ k,
            const float* __restrict__ v,
            const float* __restrict__ bias,   // [H][N][N]
            float* __restrict__ po,
            float* __restrict__ pm,
            float* __restrict__ pl)
{
    int bh = blockIdx.y;
    int b  = bh >> 3;
    int h  = bh & 7;
    int q0 = blockIdx.x * 128;
    int sz = blockIdx.z;
    int kbeg = sz * (N_ / SPLITS);            // 0 or 512
    const int NT = N_ / SPLITS / 32;          // 16 tiles

    __shared__ __align__(16) float Ks[2][32][36];
    __shared__ __align__(16) float Vs[2][32][36];

    int tid  = threadIdx.x;
    int w    = tid >> 5;
    int lane = tid & 31;
    int qrow = w * 32 + lane;          // 0..127
    int qi   = q0 + qrow;

    int fr0 = tid >> 3;                // 0..15
    int fc0 = (tid & 7) * 4;
    int fr1 = fr0 + 16;                // 16..31

    const float scale = 0.1767766952966369f;   // 1/sqrt(32)

    u64 qv2[16], o2[16];
    {
        const float4* qp = reinterpret_cast<const float4*>(
            q + ((size_t)(b * N_ + qi)) * D_ + h * DK_);
#pragma unroll
        for (int d4 = 0; d4 < 8; d4++) {
            float4 t = qp[d4];
            qv2[d4*2+0] = pk2(t.x * scale, t.y * scale);
            qv2[d4*2+1] = pk2(t.z * scale, t.w * scale);
        }
    }
#pragma unroll
    for (int d = 0; d < 16; d++) o2[d] = 0ull;
    float m = -1e30f, l = 0.0f;

    const float* brow = bias + (size_t)h * (N_ * N_) + (size_t)qi * N_ + kbeg;

    float4 kf0, kf1, vf0, vf1, bf[8];

    // prefetch tile 0
    {
        const float* kb = k + ((size_t)(b * N_ + kbeg)) * D_ + h * DK_;
        const float* vb = v + ((size_t)(b * N_ + kbeg)) * D_ + h * DK_;
        kf0 = *reinterpret_cast<const float4*>(kb + (size_t)fr0 * D_ + fc0);
        kf1 = *reinterpret_cast<const float4*>(kb + (size_t)fr1 * D_ + fc0);
        vf0 = *reinterpret_cast<const float4*>(vb + (size_t)fr0 * D_ + fc0);
        vf1 = *reinterpret_cast<const float4*>(vb + (size_t)fr1 * D_ + fc0);
#pragma unroll
        for (int j = 0; j < 8; j++)
            bf[j] = *reinterpret_cast<const float4*>(brow + j * 4);
        *reinterpret_cast<float4*>(&Ks[0][fr0][fc0]) = kf0;
        *reinterpret_cast<float4*>(&Ks[0][fr1][fc0]) = kf1;
        *reinterpret_cast<float4*>(&Vs[0][fr0][fc0]) = vf0;
        *reinterpret_cast<float4*>(&Vs[0][fr1][fc0]) = vf1;
    }
    __syncthreads();

#pragma unroll 1
    for (int t = 0; t < NT; t++) {
        int cur = t & 1;
        int k0n = kbeg + (t + 1) * 32;

        // consume bias prefetch into score init
        float s[32];
#pragma unroll
        for (int j = 0; j < 8; j++) {
            s[j*4+0] = bf[j].x; s[j*4+1] = bf[j].y;
            s[j*4+2] = bf[j].z; s[j*4+3] = bf[j].w;
        }

        // prefetch next tile (LDG latency hidden by compute below)
        if (t < NT - 1) {
            const float* kb = k + ((size_t)(b * N_ + k0n)) * D_ + h * DK_;
            const float* vb = v + ((size_t)(b * N_ + k0n)) * D_ + h * DK_;
            kf0 = *reinterpret_cast<const float4*>(kb + (size_t)fr0 * D_ + fc0);
            kf1 = *reinterpret_cast<const float4*>(kb + (size_t)fr1 * D_ + fc0);
            vf0 = *reinterpret_cast<const float4*>(vb + (size_t)fr0 * D_ + fc0);
            vf1 = *reinterpret_cast<const float4*>(vb + (size_t)fr1 * D_ + fc0);
#pragma unroll
            for (int j = 0; j < 8; j++)
                bf[j] = *reinterpret_cast<const float4*>(brow + (t + 1) * 32 + j * 4);
        }

        // scores: dual f32x2 chains per key
#pragma unroll
        for (int kk = 0; kk < 32; kk++) {
            u64 svA = 0ull, svB = 0ull;
            const ulonglong2* kr = reinterpret_cast<const ulonglong2*>(&Ks[cur][kk][0]);
#pragma unroll
            for (int p = 0; p < 8; p++) {
                ulonglong2 kp = kr[p];
                svA = fma2_(qv2[2*p + 0], kp.x, svA);
                svB = fma2_(qv2[2*p + 1], kp.y, svB);
            }
            float2 sa = upk2(svA);
            float2 sb = upk2(svB);
            s[kk] += (sa.x + sa.y) + (sb.x + sb.y);
        }

        float tmax = s[0];
#pragma unroll
        for (int kk = 1; kk < 32; kk++) tmax = fmaxf(tmax, s[kk]);
        float mnew  = fmaxf(m, tmax);
        float alpha = __expf(m - mnew);
        float psum = 0.0f;
#pragma unroll
        for (int kk = 0; kk < 32; kk++) {
            float p = __expf(s[kk] - mnew);
            s[kk] = p;
            psum += p;
        }
        l = l * alpha + psum;
        m = mnew;

        u64 al2 = pk2(alpha, alpha);
#pragma unroll
        for (int d = 0; d < 16; d++) o2[d] = mul2_(o2[d], al2);

#pragma unroll
        for (int kk = 0; kk < 32; kk++) {
            u64 p2 = pk2(s[kk], s[kk]);
            const ulonglong2* vr = reinterpret_cast<const ulonglong2*>(&Vs[cur][kk][0]);
#pragma unroll
            for (int p = 0; p < 8; p++) {
                ulonglong2 vp = vr[p];
                o2[2*p + 0] = fma2_(p2, vp.x, o2[2*p + 0]);
                o2[2*p + 1] = fma2_(p2, vp.y, o2[2*p + 1]);
            }
        }

        // stage next tile into the other buffer
        if (t < NT - 1) {
            int nxt = 1 - cur;
            *reinterpret_cast<float4*>(&Ks[nxt][fr0][fc0]) = kf0;
            *reinterpret_cast<float4*>(&Ks[nxt][fr1][fc0]) = kf1;
            *reinterpret_cast<float4*>(&Vs[nxt][fr0][fc0]) = vf0;
            *reinterpret_cast<float4*>(&Vs[nxt][fr1][fc0]) = vf1;
        }
        __syncthreads();
    }

    // store unnormalized partials
    int idx = bh * N_ + qi;               // 0..32767
    float* pob = po + ((size_t)sz * NROWS + idx) * DK_;
#pragma unroll
    for (int d4 = 0; d4 < 8; d4++) {
        float2 t0 = upk2(o2[d4*2 + 0]);
        float2 t1 = upk2(o2[d4*2 + 1]);
        float4 t = {t0.x, t0.y, t1.x, t1.y};
        *reinterpret_cast<float4*>(pob + d4 * 4) = t;
    }
    pm[sz * NROWS + idx] = m;
    pl[sz * NROWS + idx] = l;
}

// ---------------- merge split-KV partials ----------------
__global__ void __launch_bounds__(256)
merge_kernel(const float* __restrict__ po,
             const float* __restrict__ pm,
             const float* __restrict__ pl,
             float* __restrict__ out)
{
    int row  = blockIdx.x * 8 + (threadIdx.x >> 5);   // 0..32767
    int lane = threadIdx.x & 31;

    float m0 = pm[row];
    float m1 = pm[NROWS + row];
    float M  = fmaxf(m0, m1);
    float a0 = __expf(m0 - M);
    float a1 = __expf(m1 - M);
    float lsum = a0 * pl[row] + a1 * pl[NROWS + row];
    float ov = a0 * po[(size_t)row * DK_ + lane]
             + a1 * po[((size_t)NROWS + row) * DK_ + lane];
    ov /= lsum;

    int b  = row >> 13;
    int h  = (row >> 10) & 7;
    int qi = row & 1023;
    out[(((size_t)b * N_ + qi) * D_) + h * DK_ + lane] = ov;
}

// ---------------- LayerNorm over D=256 ----------------
__global__ void __launch_bounds__(256)
ln_kernel(const float* __restrict__ z,
          const float* __restrict__ g,
          const float* __restrict__ bta,
          float* __restrict__ out)
{
    int row = blockIdx.x;
    int t   = threadIdx.x;
    int lane = t & 31, wid = t >> 5;
    __shared__ float red1[8], red2[8];

    float vv = z[(size_t)row * 256 + t];
    float s = vv;
#pragma unroll
    for (int off = 16; off; off >>= 1) s += __shfl_xor_sync(0xffffffffu, s, off);
    if (lane == 0) red1[wid] = s;
    __syncthreads();
    float tot = 0.0f;
#pragma unroll
    for (int i = 0; i < 8; i++) tot += red1[i];
    float mu = tot * (1.0f / 256.0f);

    float d = vv - mu;
    float sq = d * d;
#pragma unroll
    for (int off = 16; off; off >>= 1) sq += __shfl_xor_sync(0xffffffffu, sq, off);
    if (lane == 0) red2[wid] = sq;
    __syncthreads();
    float var = 0.0f;
#pragma unroll
    for (int i = 0; i < 8; i++) var += red2[i];
    var *= (1.0f / 256.0f);

    out[(size_t)row * 256 + t] = d * rsqrtf(var + 1e-6f) * g[t] + bta[t];
}

// ---------------- launch ----------------
extern "C" void kernel_launch(void* const* d_in, const int* in_sizes, int n_in,
                              void* d_out, int out_size)
{
    (void)n_in; (void)out_size;

    const float *x, *svd_emb, *W_svd, *b_svd, *in_deg_emb, *out_deg_emb, *spatial_emb;
    const float *Wq, *Wk, *Wv, *Wa, *W1, *W2;
    const float *bq, *bk, *bv, *ba, *b1, *b2;
    const float *ln1_g, *ln1_b, *ln2_g, *ln2_b;
    const int *in_degrees, *out_degrees, *spatial_pos;

    if (in_sizes[1] == 1024) {
        // setup_inputs dict order
        x           = (const float*)d_in[0];
        in_degrees  = (const int*)  d_in[1];
        out_degrees = (const int*)  d_in[2];
        spatial_pos = (const int*)  d_in[3];
        svd_emb     = (const float*)d_in[4];
        in_deg_emb  = (const float*)d_in[5];
        out_deg_emb = (const float*)d_in[6];
        spatial_emb = (const float*)d_in[7];
        W_svd       = (const float*)d_in[8];
        b_svd       = (const float*)d_in[9];
        Wq = (const float*)d_in[10]; Wk = (const float*)d_in[11];
        Wv = (const float*)d_in[12]; Wa = (const float*)d_in[13];
        W1 = (const float*)d_in[14]; W2 = (const float*)d_in[15];
        bq = (const float*)d_in[16]; bk = (const float*)d_in[17];
        bv = (const float*)d_in[18]; ba = (const float*)d_in[19];
        b1 = (const float*)d_in[20]; b2 = (const float*)d_in[21];
        ln1_b = (const float*)d_in[22]; ln2_b = (const float*)d_in[23];
        ln1_g = (const float*)d_in[24]; ln2_g = (const float*)d_in[25];
    } else {
        // reference() signature order
        x           = (const float*)d_in[0];
        svd_emb     = (const float*)d_in[1];
        W_svd       = (const float*)d_in[2];
        b_svd       = (const float*)d_in[3];
        in_deg_emb  = (const float*)d_in[4];
        out_deg_emb = (const float*)d_in[5];
        spatial_emb = (const float*)d_in[6];
        Wq = (const float*)d_in[7];  bq = (const float*)d_in[8];
        Wk = (const float*)d_in[9];  bk = (const float*)d_in[10];
        Wv = (const float*)d_in[11]; bv = (const float*)d_in[12];
        Wa = (const float*)d_in[13]; ba = (const float*)d_in[14];
        ln1_g = (const float*)d_in[15]; ln1_b = (const float*)d_in[16];
        W1 = (const float*)d_in[17]; b1 = (const float*)d_in[18];
        W2 = (const float*)d_in[19]; b2 = (const float*)d_in[20];
        ln2_g = (const float*)d_in[21]; ln2_b = (const float*)d_in[22];
        in_degrees  = (const int*)d_in[23];
        out_degrees = (const int*)d_in[24];
        spatial_pos = (const int*)d_in[25];
    }

    float *hB, *qB, *kB, *vB, *t1B, *t2B, *nodeB, *biasB, *poB, *pmB, *plB;
    cudaGetSymbolAddress((void**)&hB,    g_h);
    cudaGetSymbolAddress((void**)&qB,    g_q);
    cudaGetSymbolAddress((void**)&kB,    g_k);
    cudaGetSymbolAddress((void**)&vB,    g_v);
    cudaGetSymbolAddress((void**)&t1B,   g_t1);
    cudaGetSymbolAddress((void**)&t2B,   g_t2);
    cudaGetSymbolAddress((void**)&nodeB, g_node);
    cudaGetSymbolAddress((void**)&biasB, g_bias);
    cudaGetSymbolAddress((void**)&poB,   g_po);
    cudaGetSymbolAddress((void**)&pmB,   g_pm);
    cudaGetSymbolAddress((void**)&plB,   g_pl);

    float* outp = (float*)d_out;

    // prologue
    node_vec_kernel<<<N_, 256>>>(svd_emb, W_svd, b_svd, in_deg_emb, out_deg_emb,
                                 in_degrees, out_degrees, nodeB);
    add_node_kernel<<<BND / 256, 256>>>(x, nodeB, hB);
    bias_kernel<<<(N_ * N_) / 256, 256>>>(spatial_pos, spatial_emb, biasB);

    dim3 ggrid(B_ * N_ / GBM, D_ / GBN);       // (32, 4)
    dim3 qkvgrid(B_ * N_ / GBM, D_ / GBN, 3);  // (32, 4, 3)
    dim3 agrid(N_ / 128, B_ * H_, SPLITS);     // (8, 32, 2) = 512 blocks

    for (int l = 0; l < L_; l++) {
        const float* wq = Wq + (size_t)l * D_ * D_;
        const float* wk = Wk + (size_t)l * D_ * D_;
        const float* wv = Wv + (size_t)l * D_ * D_;
        const float* wa = Wa + (size_t)l * D_ * D_;
        const float* w1 = W1 + (size_t)l * D_ * D_;
        const float* w2 = W2 + (size_t)l * D_ * D_;

        qkv_kernel<<<qkvgrid, 256>>>(hB, wq, wk, wv,
                                     bq + l * D_, bk + l * D_, bv + l * D_,
                                     qB, kB, vB);

        attn_kernel<<<agrid, 128>>>(qB, kB, vB, biasB, poB, pmB, plB);
        merge_kernel<<<NROWS / 8, 256>>>(poB, pmB, plB, t1B);

        gemm256_kernel<<<ggrid, 256>>>(t1B, wa, ba + l * D_, hB, t2B, 0);
        ln_kernel<<<B_ * N_, 256>>>(t2B, ln1_g + l * D_, ln1_b + l * D_, hB);

        gemm256_kernel<<<ggrid, 256>>>(hB, w1, b1 + l * D_, nullptr, t1B, 1);
        gemm256_kernel<<<ggrid, 256>>>(t1B, w2, b2 + l * D_, hB, t2B, 0);

        float* ln2_dst = (l == L_ - 1) ? outp : hB;
        ln_kernel<<<B_ * N_, 256>>>(t2B, ln2_g + l * D_, ln2_b + l * D_, ln2_dst);
    }
}

// round 12
// speedup vs baseline: 1.4797x; 1.4797x over previous
#include <cuda_runtime.h>
#include <math.h>

#define B_ 4
#define N_ 1024
#define H_ 8
#define D_ 256
#define L_ 4
#define DK_ 32
#define NSP_ 512
#define BND (B_*N_*D_)   // 1048576
#define ND  (N_*D_)      // 262144

typedef unsigned long long u64;

// ---------------- f32x2 packed-math helpers (sm_100+) ----------------
__device__ __forceinline__ u64 pk2(float x, float y) {
    u64 r; asm("mov.b64 %0, {%1, %2};" : "=l"(r) : "f"(x), "f"(y)); return r;
}
__device__ __forceinline__ float2 upk2(u64 a) {
    float2 f; asm("mov.b64 {%0, %1}, %2;" : "=f"(f.x), "=f"(f.y) : "l"(a)); return f;
}
__device__ __forceinline__ u64 fma2_(u64 a, u64 b, u64 c) {
    u64 d; asm("fma.rn.f32x2 %0, %1, %2, %3;" : "=l"(d) : "l"(a), "l"(b), "l"(c)); return d;
}
__device__ __forceinline__ u64 mul2_(u64 a, u64 b) {
    u64 d; asm("mul.rn.f32x2 %0, %1, %2;" : "=l"(d) : "l"(a), "l"(b)); return d;
}

// ---------------- scratch (static device globals; no allocation) ----------------
__device__ float g_h [BND];
__device__ float g_q [BND];
__device__ float g_k [BND];
__device__ float g_v [BND];
__device__ float g_t1[BND];
__device__ float g_t2[BND];
__device__ float g_node[ND];
__device__ float g_bias[H_ * N_ * N_];   // 32MB precomputed bias [H][N][N]

// ---------------- prologue: node-level embeddings ----------------
__global__ void node_vec_kernel(const float* __restrict__ svd_emb,
                                const float* __restrict__ W_svd,
                                const float* __restrict__ b_svd,
                                const float* __restrict__ in_deg_emb,
                                const float* __restrict__ out_deg_emb,
                                const int*   __restrict__ in_degrees,
                                const int*   __restrict__ out_degrees,
                                float* __restrict__ nodevec)
{
    int n = blockIdx.x;
    int d = threadIdx.x;           // 256 threads
    __shared__ float pos[32];
    if (d < 32) {
        float v = svd_emb[n * 32 + d];
        pos[d] = (d < 16) ? v : -v;
    }
    __syncthreads();
    int in_i  = in_degrees[n];
    int out_i = out_degrees[n];
    float acc = b_svd[d] + in_deg_emb[in_i * D_ + d] + out_deg_emb[out_i * D_ + d];
#pragma unroll
    for (int k = 0; k < 32; k++)
        acc += pos[k] * W_svd[k * D_ + d];
    nodevec[n * D_ + d] = acc;
}

__global__ void add_node_kernel(const float* __restrict__ x,
                                const float* __restrict__ nodevec,
                                float* __restrict__ h)
{
    int i = blockIdx.x * blockDim.x + threadIdx.x;
    h[i] = x[i] + nodevec[i & (ND - 1)];
}

// ---------------- precompute attention bias ----------------
__global__ void bias_kernel(const int* __restrict__ spatial_pos,
                            const float* __restrict__ spatial_emb,
                            float* __restrict__ bias)
{
    int i = blockIdx.x * 256 + threadIdx.x;     // over N*N = 1M
    int s = spatial_pos[i];
#pragma unroll
    for (int h = 0; h < H_; h++)
        bias[(size_t)h * (N_ * N_) + i] = spatial_emb[s * H_ + h];
}

// ---------------- GEMM: 128x64 tile, 256 threads, 8m x 4n microtile, f32x2 ----------------
#define GBM 128
#define GBN 64
#define GBK 16
__device__ __forceinline__ void gemm_body(const float* __restrict__ A,
                                          const float* __restrict__ W,
                                          const float* __restrict__ bias,
                                          const float* __restrict__ res,
                                          float* __restrict__ out,
                                          int relu, int bm, int bn)
{
    __shared__ __align__(16) float As[GBK][GBM + 4];  // [16][132]
    __shared__ __align__(16) float Bs[GBK][GBN];      // [16][64]

    int tid = threadIdx.x;            // 256
    int tx = tid & 15;                // n dir: 4 cols
    int ty = tid >> 4;                // m dir: 8 rows (4 f32x2 pairs)

    int ar = tid >> 1;                // A row 0..127
    int ac = (tid & 1) * 8;           // A k-chunk 0 or 8
    int br = tid >> 4;                // B k-row 0..15
    int bc = (tid & 15) * 4;          // B n-chunk

    const float* Ap = A + (size_t)(bm + ar) * 256 + ac;
    const float* Wp = W + (size_t)br * 256 + bn + bc;

    float4 a0 = *reinterpret_cast<const float4*>(Ap);
    float4 a1 = *reinterpret_cast<const float4*>(Ap + 4);
    float4 b0 = *reinterpret_cast<const float4*>(Wp);

    u64 acc2[4][4] = {};   // [m-pair p -> rows ty*8+2p,+2p+1][n j]

#pragma unroll 1
    for (int k0 = 0; k0 < 256; k0 += GBK) {
        As[ac + 0][ar] = a0.x; As[ac + 1][ar] = a0.y;
        As[ac + 2][ar] = a0.z; As[ac + 3][ar] = a0.w;
        As[ac + 4][ar] = a1.x; As[ac + 5][ar] = a1.y;
        As[ac + 6][ar] = a1.z; As[ac + 7][ar] = a1.w;
        *reinterpret_cast<float4*>(&Bs[br][bc]) = b0;
        __syncthreads();
        if (k0 + GBK < 256) {
            a0 = *reinterpret_cast<const float4*>(Ap + k0 + GBK);
            a1 = *reinterpret_cast<const float4*>(Ap + k0 + GBK + 4);
            b0 = *reinterpret_cast<const float4*>(Wp + (size_t)(k0 + GBK) * 256);
        }
#pragma unroll
        for (int kk = 0; kk < GBK; kk++) {
            ulonglong2 aA = *reinterpret_cast<const ulonglong2*>(&As[kk][ty * 8]);
            ulonglong2 aB = *reinterpret_cast<const ulonglong2*>(&As[kk][ty * 8 + 4]);
            float4 b4 = *reinterpret_cast<const float4*>(&Bs[kk][tx * 4]);
            u64 bd[4];
            bd[0] = pk2(b4.x, b4.x); bd[1] = pk2(b4.y, b4.y);
            bd[2] = pk2(b4.z, b4.z); bd[3] = pk2(b4.w, b4.w);
            u64 am[4] = {aA.x, aA.y, aB.x, aB.y};
#pragma unroll
            for (int p = 0; p < 4; p++)
#pragma unroll
                for (int j = 0; j < 4; j++)
                    acc2[p][j] = fma2_(am[p], bd[j], acc2[p][j]);
        }
        __syncthreads();
    }

    int n = bn + tx * 4;
    float4 bb = *reinterpret_cast<const float4*>(bias + n);
#pragma unroll
    for (int p = 0; p < 4; p++) {
#pragma unroll
        for (int half = 0; half < 2; half++) {
            int m = bm + ty * 8 + p * 2 + half;
            float4 vv;
            {
                float2 t0 = upk2(acc2[p][0]);
                float2 t1 = upk2(acc2[p][1]);
                float2 t2 = upk2(acc2[p][2]);
                float2 t3 = upk2(acc2[p][3]);
                if (half) { vv.x = t0.y; vv.y = t1.y; vv.z = t2.y; vv.w = t3.y; }
                else      { vv.x = t0.x; vv.y = t1.x; vv.z = t2.x; vv.w = t3.x; }
            }
            vv.x += bb.x; vv.y += bb.y; vv.z += bb.z; vv.w += bb.w;
            if (res) {
                float4 rr = *reinterpret_cast<const float4*>(res + (size_t)m * 256 + n);
                vv.x += rr.x; vv.y += rr.y; vv.z += rr.z; vv.w += rr.w;
            }
            if (relu) {
                vv.x = fmaxf(vv.x, 0.f); vv.y = fmaxf(vv.y, 0.f);
                vv.z = fmaxf(vv.z, 0.f); vv.w = fmaxf(vv.w, 0.f);
            }
            *reinterpret_cast<float4*>(out + (size_t)m * 256 + n) = vv;
        }
    }
}

__global__ void __launch_bounds__(256)
gemm256_kernel(const float* __restrict__ A, const float* __restrict__ W,
               const float* __restrict__ bias, const float* __restrict__ res,
               float* __restrict__ out, int relu)
{
    gemm_body(A, W, bias, res, out, relu, blockIdx.x * GBM, blockIdx.y * GBN);
}

__global__ void __launch_bounds__(256)
qkv_kernel(const float* __restrict__ A,
           const float* __restrict__ Wq, const float* __restrict__ Wk, const float* __restrict__ Wv,
           const float* __restrict__ bq, const float* __restrict__ bk, const float* __restrict__ bv,
           float* __restrict__ q, float* __restrict__ k, float* __restrict__ v)
{
    const float* W; const float* bias; float* out;
    if (blockIdx.z == 0)      { W = Wq; bias = bq; out = q; }
    else if (blockIdx.z == 1) { W = Wk; bias = bk; out = k; }
    else                      { W = Wv; bias = bv; out = v; }
    gemm_body(A, W, bias, nullptr, out, 0, blockIdx.x * GBM, blockIdx.y * GBN);
}

// ---------------- flash attention: half-warp key-split, double-buffered K/V ----------------
// grid: (N/64, B*H), block 128 (4 warps). Warp w owns 16 queries (q0+w*16 .. +15).
// Lanes L and L+16 handle the SAME query, complementary 16-key halves of each tile.
__global__ void __launch_bounds__(128)
attn_kernel(const float* __restrict__ q,
            const float* __restrict__ k,
            const float* __restrict__ v,
            const float* __restrict__ bias,   // [H][N][N]
            float* __restrict__ out)
{
    int bh = blockIdx.y;
    int b  = bh >> 3;
    int h  = bh & 7;
    int q0 = blockIdx.x * 64;

    __shared__ __align__(16) float Ks[2][32][36];
    __shared__ __align__(16) float Vs[2][32][36];

    int tid   = threadIdx.x;
    int w     = tid >> 5;
    int lane  = tid & 31;
    int ql    = lane & 15;             // query within warp (0..15)
    int khalf = lane >> 4;             // 0 or 1: which 16-key half of a tile
    int koff  = khalf * 16;            // key offset within a 32-key tile
    int qi    = q0 + w * 16 + ql;

    // fill indices (same as R8): each thread stages 2 rows of K and V
    int fr0 = tid >> 3;                // 0..15
    int fc0 = (tid & 7) * 4;
    int fr1 = fr0 + 16;                // 16..31

    const float scale = 0.1767766952966369f;   // 1/sqrt(32)

    u64 qv2[16], o2[16];
    {
        const float4* qp = reinterpret_cast<const float4*>(
            q + ((size_t)(b * N_ + qi)) * D_ + h * DK_);
#pragma unroll
        for (int d4 = 0; d4 < 8; d4++) {
            float4 t = qp[d4];
            qv2[d4*2+0] = pk2(t.x * scale, t.y * scale);
            qv2[d4*2+1] = pk2(t.z * scale, t.w * scale);
        }
    }
#pragma unroll
    for (int d = 0; d < 16; d++) o2[d] = 0ull;
    float m = -1e30f, l = 0.0f;

    const float* brow = bias + (size_t)h * (N_ * N_) + (size_t)qi * N_ + koff;

    float4 kf0, kf1, vf0, vf1, bf[4];

    // prefetch tile 0
    {
        const float* kb = k + ((size_t)(b * N_)) * D_ + h * DK_;
        const float* vb = v + ((size_t)(b * N_)) * D_ + h * DK_;
        kf0 = *reinterpret_cast<const float4*>(kb + (size_t)fr0 * D_ + fc0);
        kf1 = *reinterpret_cast<const float4*>(kb + (size_t)fr1 * D_ + fc0);
        vf0 = *reinterpret_cast<const float4*>(vb + (size_t)fr0 * D_ + fc0);
        vf1 = *reinterpret_cast<const float4*>(vb + (size_t)fr1 * D_ + fc0);
#pragma unroll
        for (int j = 0; j < 4; j++)
            bf[j] = *reinterpret_cast<const float4*>(brow + j * 4);
        *reinterpret_cast<float4*>(&Ks[0][fr0][fc0]) = kf0;
        *reinterpret_cast<float4*>(&Ks[0][fr1][fc0]) = kf1;
        *reinterpret_cast<float4*>(&Vs[0][fr0][fc0]) = vf0;
        *reinterpret_cast<float4*>(&Vs[0][fr1][fc0]) = vf1;
    }
    __syncthreads();

#pragma unroll 1
    for (int t = 0; t < 32; t++) {
        int cur = t & 1;
        int k0n = (t + 1) * 32;

        // consume bias prefetch into score init (this lane's 16 keys)
        float s[16];
#pragma unroll
        for (int j = 0; j < 4; j++) {
            s[j*4+0] = bf[j].x; s[j*4+1] = bf[j].y;
            s[j*4+2] = bf[j].z; s[j*4+3] = bf[j].w;
        }

        // prefetch next tile (LDG latency hidden by compute below)
        if (t < 31) {
            const float* kb = k + ((size_t)(b * N_ + k0n)) * D_ + h * DK_;
            const float* vb = v + ((size_t)(b * N_ + k0n)) * D_ + h * DK_;
            kf0 = *reinterpret_cast<const float4*>(kb + (size_t)fr0 * D_ + fc0);
            kf1 = *reinterpret_cast<const float4*>(kb + (size_t)fr1 * D_ + fc0);
            vf0 = *reinterpret_cast<const float4*>(vb + (size_t)fr0 * D_ + fc0);
            vf1 = *reinterpret_cast<const float4*>(vb + (size_t)fr1 * D_ + fc0);
#pragma unroll
            for (int j = 0; j < 4; j++)
                bf[j] = *reinterpret_cast<const float4*>(brow + k0n + j * 4);
        }

        // scores for this lane's 16 keys: dual f32x2 chains per key
#pragma unroll
        for (int j = 0; j < 16; j++) {
            int kk = koff + j;
            u64 svA = 0ull, svB = 0ull;
            const ulonglong2* kr = reinterpret_cast<const ulonglong2*>(&Ks[cur][kk][0]);
#pragma unroll
            for (int p = 0; p < 8; p++) {
                ulonglong2 kp = kr[p];
                svA = fma2_(qv2[2*p + 0], kp.x, svA);
                svB = fma2_(qv2[2*p + 1], kp.y, svB);
            }
            float2 sa = upk2(svA);
            float2 sb = upk2(svB);
            s[j] += (sa.x + sa.y) + (sb.x + sb.y);
        }

        // combine tile max with partner lane (same query, other key half)
        float tmax = s[0];
#pragma unroll
        for (int j = 1; j < 16; j++) tmax = fmaxf(tmax, s[j]);
        tmax = fmaxf(tmax, __shfl_xor_sync(0xffffffffu, tmax, 16));
        float mnew  = fmaxf(m, tmax);
        float alpha = __expf(m - mnew);
        float psum = 0.0f;
#pragma unroll
        for (int j = 0; j < 16; j++) {
            float p = __expf(s[j] - mnew);
            s[j] = p;
            psum += p;
        }
        psum += __shfl_xor_sync(0xffffffffu, psum, 16);
        l = l * alpha + psum;
        m = mnew;

        u64 al2 = pk2(alpha, alpha);
#pragma unroll
        for (int d = 0; d < 16; d++) o2[d] = mul2_(o2[d], al2);

#pragma unroll
        for (int j = 0; j < 16; j++) {
            int kk = koff + j;
            u64 p2 = pk2(s[j], s[j]);
            const ulonglong2* vr = reinterpret_cast<const ulonglong2*>(&Vs[cur][kk][0]);
#pragma unroll
            for (int p = 0; p < 8; p++) {
                ulonglong2 vp = vr[p];
                o2[2*p + 0] = fma2_(p2, vp.x, o2[2*p + 0]);
                o2[2*p + 1] = fma2_(p2, vp.y, o2[2*p + 1]);
            }
        }

        // stage next tile into the other buffer
        if (t < 31) {
            int nxt = 1 - cur;
            *reinterpret_cast<float4*>(&Ks[nxt][fr0][fc0]) = kf0;
            *reinterpret_cast<float4*>(&Ks[nxt][fr1][fc0]) = kf1;
            *reinterpret_cast<float4*>(&Vs[nxt][fr0][fc0]) = vf0;
            *reinterpret_cast<float4*>(&Vs[nxt][fr1][fc0]) = vf1;
        }
        __syncthreads();
    }

    // combine o across partner lanes (l is already the full sum on both lanes)
    float ov[32];
#pragma unroll
    for (int d4 = 0; d4 < 16; d4++) {
        float2 t2 = upk2(o2[d4]);
        ov[d4*2 + 0] = t2.x;
        ov[d4*2 + 1] = t2.y;
    }
#pragma unroll
    for (int d = 0; d < 32; d++)
        ov[d] += __shfl_xor_sync(0xffffffffu, ov[d], 16);

    if (khalf == 0) {
        float inv = 1.0f / l;
        float* ob = out + ((size_t)(b * N_ + qi)) * D_ + h * DK_;
#pragma unroll
        for (int d4 = 0; d4 < 8; d4++) {
            float4 t;
            t.x = ov[d4*4+0] * inv; t.y = ov[d4*4+1] * inv;
            t.z = ov[d4*4+2] * inv; t.w = ov[d4*4+3] * inv;
            *reinterpret_cast<float4*>(ob + d4 * 4) = t;
        }
    }
}

// ---------------- LayerNorm over D=256 ----------------
__global__ void __launch_bounds__(256)
ln_kernel(const float* __restrict__ z,
          const float* __restrict__ g,
          const float* __restrict__ bta,
          float* __restrict__ out)
{
    int row = blockIdx.x;
    int t   = threadIdx.x;
    int lane = t & 31, wid = t >> 5;
    __shared__ float red1[8], red2[8];

    float vv = z[(size_t)row * 256 + t];
    float s = vv;
#pragma unroll
    for (int off = 16; off; off >>= 1) s += __shfl_xor_sync(0xffffffffu, s, off);
    if (lane == 0) red1[wid] = s;
    __syncthreads();
    float tot = 0.0f;
#pragma unroll
    for (int i = 0; i < 8; i++) tot += red1[i];
    float mu = tot * (1.0f / 256.0f);

    float d = vv - mu;
    float sq = d * d;
#pragma unroll
    for (int off = 16; off; off >>= 1) sq += __shfl_xor_sync(0xffffffffu, sq, off);
    if (lane == 0) red2[wid] = sq;
    __syncthreads();
    float var = 0.0f;
#pragma unroll
    for (int i = 0; i < 8; i++) var += red2[i];
    var *= (1.0f / 256.0f);

    out[(size_t)row * 256 + t] = d * rsqrtf(var + 1e-6f) * g[t] + bta[t];
}

// ---------------- launch ----------------
extern "C" void kernel_launch(void* const* d_in, const int* in_sizes, int n_in,
                              void* d_out, int out_size)
{
    (void)n_in; (void)out_size;

    const float *x, *svd_emb, *W_svd, *b_svd, *in_deg_emb, *out_deg_emb, *spatial_emb;
    const float *Wq, *Wk, *Wv, *Wa, *W1, *W2;
    const float *bq, *bk, *bv, *ba, *b1, *b2;
    const float *ln1_g, *ln1_b, *ln2_g, *ln2_b;
    const int *in_degrees, *out_degrees, *spatial_pos;

    if (in_sizes[1] == 1024) {
        // setup_inputs dict order
        x           = (const float*)d_in[0];
        in_degrees  = (const int*)  d_in[1];
        out_degrees = (const int*)  d_in[2];
        spatial_pos = (const int*)  d_in[3];
        svd_emb     = (const float*)d_in[4];
        in_deg_emb  = (const float*)d_in[5];
        out_deg_emb = (const float*)d_in[6];
        spatial_emb = (const float*)d_in[7];
        W_svd       = (const float*)d_in[8];
        b_svd       = (const float*)d_in[9];
        Wq = (const float*)d_in[10]; Wk = (const float*)d_in[11];
        Wv = (const float*)d_in[12]; Wa = (const float*)d_in[13];
        W1 = (const float*)d_in[14]; W2 = (const float*)d_in[15];
        bq = (const float*)d_in[16]; bk = (const float*)d_in[17];
        bv = (const float*)d_in[18]; ba = (const float*)d_in[19];
        b1 = (const float*)d_in[20]; b2 = (const float*)d_in[21];
        ln1_b = (const float*)d_in[22]; ln2_b = (const float*)d_in[23];
        ln1_g = (const float*)d_in[24]; ln2_g = (const float*)d_in[25];
    } else {
        // reference() signature order
        x           = (const float*)d_in[0];
        svd_emb     = (const float*)d_in[1];
        W_svd       = (const float*)d_in[2];
        b_svd       = (const float*)d_in[3];
        in_deg_emb  = (const float*)d_in[4];
        out_deg_emb = (const float*)d_in[5];
        spatial_emb = (const float*)d_in[6];
        Wq = (const float*)d_in[7];  bq = (const float*)d_in[8];
        Wk = (const float*)d_in[9];  bk = (const float*)d_in[10];
        Wv = (const float*)d_in[11]; bv = (const float*)d_in[12];
        Wa = (const float*)d_in[13]; ba = (const float*)d_in[14];
        ln1_g = (const float*)d_in[15]; ln1_b = (const float*)d_in[16];
        W1 = (const float*)d_in[17]; b1 = (const float*)d_in[18];
        W2 = (const float*)d_in[19]; b2 = (const float*)d_in[20];
        ln2_g = (const float*)d_in[21]; ln2_b = (const float*)d_in[22];
        in_degrees  = (const int*)d_in[23];
        out_degrees = (const int*)d_in[24];
        spatial_pos = (const int*)d_in[25];
    }

    float *hB, *qB, *kB, *vB, *t1B, *t2B, *nodeB, *biasB;
    cudaGetSymbolAddress((void**)&hB,    g_h);
    cudaGetSymbolAddress((void**)&qB,    g_q);
    cudaGetSymbolAddress((void**)&kB,    g_k);
    cudaGetSymbolAddress((void**)&vB,    g_v);
    cudaGetSymbolAddress((void**)&t1B,   g_t1);
    cudaGetSymbolAddress((void**)&t2B,   g_t2);
    cudaGetSymbolAddress((void**)&nodeB, g_node);
    cudaGetSymbolAddress((void**)&biasB, g_bias);

    float* outp = (float*)d_out;

    // prologue
    node_vec_kernel<<<N_, 256>>>(svd_emb, W_svd, b_svd, in_deg_emb, out_deg_emb,
                                 in_degrees, out_degrees, nodeB);
    add_node_kernel<<<BND / 256, 256>>>(x, nodeB, hB);
    bias_kernel<<<(N_ * N_) / 256, 256>>>(spatial_pos, spatial_emb, biasB);

    dim3 ggrid(B_ * N_ / GBM, D_ / GBN);       // (32, 4)
    dim3 qkvgrid(B_ * N_ / GBM, D_ / GBN, 3);  // (32, 4, 3)
    dim3 agrid(N_ / 64, B_ * H_);              // (16, 32) = 512 blocks

    for (int l = 0; l < L_; l++) {
        const float* wq = Wq + (size_t)l * D_ * D_;
        const float* wk = Wk + (size_t)l * D_ * D_;
        const float* wv = Wv + (size_t)l * D_ * D_;
        const float* wa = Wa + (size_t)l * D_ * D_;
        const float* w1 = W1 + (size_t)l * D_ * D_;
        const float* w2 = W2 + (size_t)l * D_ * D_;

        qkv_kernel<<<qkvgrid, 256>>>(hB, wq, wk, wv,
                                     bq + l * D_, bk + l * D_, bv + l * D_,
                                     qB, kB, vB);

        attn_kernel<<<agrid, 128>>>(qB, kB, vB, biasB, t1B);

        gemm256_kernel<<<ggrid, 256>>>(t1B, wa, ba + l * D_, hB, t2B, 0);
        ln_kernel<<<B_ * N_, 256>>>(t2B, ln1_g + l * D_, ln1_b + l * D_, hB);

        gemm256_kernel<<<ggrid, 256>>>(hB, w1, b1 + l * D_, nullptr, t1B, 1);
        gemm256_kernel<<<ggrid, 256>>>(t1B, w2, b2 + l * D_, hB, t2B, 0);

        float* ln2_dst = (l == L_ - 1) ? outp : hB;
        ln_kernel<<<B_ * N_, 256>>>(t2B, ln2_g + l * D_, ln2_b + l * D_, ln2_dst);
    }
}

// round 13
// speedup vs baseline: 1.6456x; 1.1121x over previous
#include <cuda_runtime.h>
#include <math.h>

#define B_ 4
#define N_ 1024
#define H_ 8
#define D_ 256
#define L_ 4
#define DK_ 32
#define NSP_ 512
#define BND (B_*N_*D_)   // 1048576
#define ND  (N_*D_)      // 262144

typedef unsigned long long u64;

// ---------------- f32x2 packed-math helpers (sm_100+) ----------------
__device__ __forceinline__ u64 pk2(float x, float y) {
    u64 r; asm("mov.b64 %0, {%1, %2};" : "=l"(r) : "f"(x), "f"(y)); return r;
}
__device__ __forceinline__ float2 upk2(u64 a) {
    float2 f; asm("mov.b64 {%0, %1}, %2;" : "=f"(f.x), "=f"(f.y) : "l"(a)); return f;
}
__device__ __forceinline__ u64 fma2_(u64 a, u64 b, u64 c) {
    u64 d; asm("fma.rn.f32x2 %0, %1, %2, %3;" : "=l"(d) : "l"(a), "l"(b), "l"(c)); return d;
}
__device__ __forceinline__ u64 mul2_(u64 a, u64 b) {
    u64 d; asm("mul.rn.f32x2 %0, %1, %2;" : "=l"(d) : "l"(a), "l"(b)); return d;
}

// ---------------- scratch (static device globals; no allocation) ----------------
__device__ float g_h [BND];
__device__ float g_q [BND];
__device__ float g_k [BND];
__device__ float g_v [BND];
__device__ float g_t1[BND];
__device__ float g_t2[BND];
__device__ float g_node[ND];
__device__ float g_bias[H_ * N_ * N_];   // 32MB precomputed bias [H][N][N], scaled by log2(e)

// ---------------- prologue: node-level embeddings ----------------
__global__ void node_vec_kernel(const float* __restrict__ svd_emb,
                                const float* __restrict__ W_svd,
                                const float* __restrict__ b_svd,
                                const float* __restrict__ in_deg_emb,
                                const float* __restrict__ out_deg_emb,
                                const int*   __restrict__ in_degrees,
                                const int*   __restrict__ out_degrees,
                                float* __restrict__ nodevec)
{
    int n = blockIdx.x;
    int d = threadIdx.x;           // 256 threads
    __shared__ float pos[32];
    if (d < 32) {
        float v = svd_emb[n * 32 + d];
        pos[d] = (d < 16) ? v : -v;
    }
    __syncthreads();
    int in_i  = in_degrees[n];
    int out_i = out_degrees[n];
    float acc = b_svd[d] + in_deg_emb[in_i * D_ + d] + out_deg_emb[out_i * D_ + d];
#pragma unroll
    for (int k = 0; k < 32; k++)
        acc += pos[k] * W_svd[k * D_ + d];
    nodevec[n * D_ + d] = acc;
}

__global__ void add_node_kernel(const float* __restrict__ x,
                                const float* __restrict__ nodevec,
                                float* __restrict__ h)
{
    int i = blockIdx.x * blockDim.x + threadIdx.x;
    h[i] = x[i] + nodevec[i & (ND - 1)];
}

// ---------------- precompute attention bias (scaled by log2(e) for exp2 softmax) ----
__global__ void bias_kernel(const int* __restrict__ spatial_pos,
                            const float* __restrict__ spatial_emb,
                            float* __restrict__ bias)
{
    const float LOG2E = 1.4426950408889634f;
    int i = blockIdx.x * 256 + threadIdx.x;     // over N*N = 1M
    int s = spatial_pos[i];
#pragma unroll
    for (int h = 0; h < H_; h++)
        bias[(size_t)h * (N_ * N_) + i] = spatial_emb[s * H_ + h] * LOG2E;
}

// ---------------- GEMM: 128x64 tile, 256 threads, 8m x 4n microtile, f32x2 ----------------
#define GBM 128
#define GBN 64
#define GBK 16
__device__ __forceinline__ void gemm_body(const float* __restrict__ A,
                                          const float* __restrict__ W,
                                          const float* __restrict__ bias,
                                          const float* __restrict__ res,
                                          float* __restrict__ out,
                                          int relu, int bm, int bn)
{
    __shared__ __align__(16) float As[GBK][GBM + 4];  // [16][132]
    __shared__ __align__(16) float Bs[GBK][GBN];      // [16][64]

    int tid = threadIdx.x;            // 256
    int tx = tid & 15;                // n dir: 4 cols
    int ty = tid >> 4;                // m dir: 8 rows (4 f32x2 pairs)

    int ar = tid >> 1;                // A row 0..127
    int ac = (tid & 1) * 8;           // A k-chunk 0 or 8
    int br = tid >> 4;                // B k-row 0..15
    int bc = (tid & 15) * 4;          // B n-chunk

    const float* Ap = A + (size_t)(bm + ar) * 256 + ac;
    const float* Wp = W + (size_t)br * 256 + bn + bc;

    float4 a0 = *reinterpret_cast<const float4*>(Ap);
    float4 a1 = *reinterpret_cast<const float4*>(Ap + 4);
    float4 b0 = *reinterpret_cast<const float4*>(Wp);

    u64 acc2[4][4] = {};   // [m-pair p -> rows ty*8+2p,+2p+1][n j]

#pragma unroll 1
    for (int k0 = 0; k0 < 256; k0 += GBK) {
        As[ac + 0][ar] = a0.x; As[ac + 1][ar] = a0.y;
        As[ac + 2][ar] = a0.z; As[ac + 3][ar] = a0.w;
        As[ac + 4][ar] = a1.x; As[ac + 5][ar] = a1.y;
        As[ac + 6][ar] = a1.z; As[ac + 7][ar] = a1.w;
        *reinterpret_cast<float4*>(&Bs[br][bc]) = b0;
        __syncthreads();
        if (k0 + GBK < 256) {
            a0 = *reinterpret_cast<const float4*>(Ap + k0 + GBK);
            a1 = *reinterpret_cast<const float4*>(Ap + k0 + GBK + 4);
            b0 = *reinterpret_cast<const float4*>(Wp + (size_t)(k0 + GBK) * 256);
        }
#pragma unroll
        for (int kk = 0; kk < GBK; kk++) {
            ulonglong2 aA = *reinterpret_cast<const ulonglong2*>(&As[kk][ty * 8]);
            ulonglong2 aB = *reinterpret_cast<const ulonglong2*>(&As[kk][ty * 8 + 4]);
            float4 b4 = *reinterpret_cast<const float4*>(&Bs[kk][tx * 4]);
            u64 bd[4];
            bd[0] = pk2(b4.x, b4.x); bd[1] = pk2(b4.y, b4.y);
            bd[2] = pk2(b4.z, b4.z); bd[3] = pk2(b4.w, b4.w);
            u64 am[4] = {aA.x, aA.y, aB.x, aB.y};
#pragma unroll
            for (int p = 0; p < 4; p++)
#pragma unroll
                for (int j = 0; j < 4; j++)
                    acc2[p][j] = fma2_(am[p], bd[j], acc2[p][j]);
        }
        __syncthreads();
    }

    int n = bn + tx * 4;
    float4 bb = *reinterpret_cast<const float4*>(bias + n);
#pragma unroll
    for (int p = 0; p < 4; p++) {
#pragma unroll
        for (int half = 0; half < 2; half++) {
            int m = bm + ty * 8 + p * 2 + half;
            float4 vv;
            {
                float2 t0 = upk2(acc2[p][0]);
                float2 t1 = upk2(acc2[p][1]);
                float2 t2 = upk2(acc2[p][2]);
                float2 t3 = upk2(acc2[p][3]);
                if (half) { vv.x = t0.y; vv.y = t1.y; vv.z = t2.y; vv.w = t3.y; }
                else      { vv.x = t0.x; vv.y = t1.x; vv.z = t2.x; vv.w = t3.x; }
            }
            vv.x += bb.x; vv.y += bb.y; vv.z += bb.z; vv.w += bb.w;
            if (res) {
                float4 rr = *reinterpret_cast<const float4*>(res + (size_t)m * 256 + n);
                vv.x += rr.x; vv.y += rr.y; vv.z += rr.z; vv.w += rr.w;
            }
            if (relu) {
                vv.x = fmaxf(vv.x, 0.f); vv.y = fmaxf(vv.y, 0.f);
                vv.z = fmaxf(vv.z, 0.f); vv.w = fmaxf(vv.w, 0.f);
            }
            *reinterpret_cast<float4*>(out + (size_t)m * 256 + n) = vv;
        }
    }
}

__global__ void __launch_bounds__(256)
gemm256_kernel(const float* __restrict__ A, const float* __restrict__ W,
               const float* __restrict__ bias, const float* __restrict__ res,
               float* __restrict__ out, int relu)
{
    gemm_body(A, W, bias, res, out, relu, blockIdx.x * GBM, blockIdx.y * GBN);
}

__global__ void __launch_bounds__(256)
qkv_kernel(const float* __restrict__ A,
           const float* __restrict__ Wq, const float* __restrict__ Wk, const float* __restrict__ Wv,
           const float* __restrict__ bq, const float* __restrict__ bk, const float* __restrict__ bv,
           float* __restrict__ q, float* __restrict__ k, float* __restrict__ v)
{
    const float* W; const float* bias; float* out;
    if (blockIdx.z == 0)      { W = Wq; bias = bq; out = q; }
    else if (blockIdx.z == 1) { W = Wk; bias = bk; out = k; }
    else                      { W = Wv; bias = bv; out = v; }
    gemm_body(A, W, bias, nullptr, out, 0, blockIdx.x * GBM, blockIdx.y * GBN);
}

// ---------------- flash attention: lane = query, double-buffered K/V, reg bias ----------------
// grid: (N/128, B*H), block 128. Warp w owns query q0 + w*32 + lane.
// Softmax in exp2 domain (q prescaled by scale*log2e, bias table prescaled by log2e).
__global__ void __launch_bounds__(128)
attn_kernel(const float* __restrict__ q,
            const float* __restrict__ k,
            const float* __restrict__ v,
            const float* __restrict__ bias,   // [H][N][N], log2e-scaled
            float* __restrict__ out)
{
    int bh = blockIdx.y;
    int b  = bh >> 3;
    int h  = bh & 7;
    int q0 = blockIdx.x * 128;

    __shared__ __align__(16) float Ks[2][32][36];
    __shared__ __align__(16) float Vs[2][32][36];

    int tid  = threadIdx.x;
    int w    = tid >> 5;
    int lane = tid & 31;
    int qrow = w * 32 + lane;          // 0..127
    int qi   = q0 + qrow;

    // fill indices (fixed per thread)
    int fr0 = tid >> 3;                // 0..15
    int fc0 = (tid & 7) * 4;
    int fr1 = fr0 + 16;                // 16..31

    const float scale = 0.1767766952966369f * 1.4426950408889634f;  // (1/sqrt(32))*log2(e)

    u64 qv2[16], o2[16];
    {
        const float4* qp = reinterpret_cast<const float4*>(
            q + ((size_t)(b * N_ + qi)) * D_ + h * DK_);
#pragma unroll
        for (int d4 = 0; d4 < 8; d4++) {
            float4 t = qp[d4];
            qv2[d4*2+0] = pk2(t.x * scale, t.y * scale);
            qv2[d4*2+1] = pk2(t.z * scale, t.w * scale);
        }
    }
#pragma unroll
    for (int d = 0; d < 16; d++) o2[d] = 0ull;
    float m = -1e30f, l = 0.0f;

    const float* brow = bias + (size_t)h * (N_ * N_) + (size_t)qi * N_;

    float4 kf0, kf1, vf0, vf1, bf[8];

    // prefetch tile 0
    {
        const float* kb = k + ((size_t)(b * N_)) * D_ + h * DK_;
        const float* vb = v + ((size_t)(b * N_)) * D_ + h * DK_;
        kf0 = *reinterpret_cast<const float4*>(kb + (size_t)fr0 * D_ + fc0);
        kf1 = *reinterpret_cast<const float4*>(kb + (size_t)fr1 * D_ + fc0);
        vf0 = *reinterpret_cast<const float4*>(vb + (size_t)fr0 * D_ + fc0);
        vf1 = *reinterpret_cast<const float4*>(vb + (size_t)fr1 * D_ + fc0);
#pragma unroll
        for (int j = 0; j < 8; j++)
            bf[j] = *reinterpret_cast<const float4*>(brow + j * 4);
        *reinterpret_cast<float4*>(&Ks[0][fr0][fc0]) = kf0;
        *reinterpret_cast<float4*>(&Ks[0][fr1][fc0]) = kf1;
        *reinterpret_cast<float4*>(&Vs[0][fr0][fc0]) = vf0;
        *reinterpret_cast<float4*>(&Vs[0][fr1][fc0]) = vf1;
    }
    __syncthreads();

#pragma unroll 1
    for (int t = 0; t < 32; t++) {
        int cur = t & 1;
        int k0n = (t + 1) * 32;

        // consume bias prefetch into score init
        float s[32];
#pragma unroll
        for (int j = 0; j < 8; j++) {
            s[j*4+0] = bf[j].x; s[j*4+1] = bf[j].y;
            s[j*4+2] = bf[j].z; s[j*4+3] = bf[j].w;
        }

        // prefetch next tile (LDG latency hidden by compute below)
        if (t < 31) {
            const float* kb = k + ((size_t)(b * N_ + k0n)) * D_ + h * DK_;
            const float* vb = v + ((size_t)(b * N_ + k0n)) * D_ + h * DK_;
            kf0 = *reinterpret_cast<const float4*>(kb + (size_t)fr0 * D_ + fc0);
            kf1 = *reinterpret_cast<const float4*>(kb + (size_t)fr1 * D_ + fc0);
            vf0 = *reinterpret_cast<const float4*>(vb + (size_t)fr0 * D_ + fc0);
            vf1 = *reinterpret_cast<const float4*>(vb + (size_t)fr1 * D_ + fc0);
#pragma unroll
            for (int j = 0; j < 8; j++)
                bf[j] = *reinterpret_cast<const float4*>(brow + k0n + j * 4);
        }

        // scores: dual f32x2 chains per key (log2 domain)
#pragma unroll
        for (int kk = 0; kk < 32; kk++) {
            u64 svA = 0ull, svB = 0ull;
            const ulonglong2* kr = reinterpret_cast<const ulonglong2*>(&Ks[cur][kk][0]);
#pragma unroll
            for (int p = 0; p < 8; p++) {
                ulonglong2 kp = kr[p];
                svA = fma2_(qv2[2*p + 0], kp.x, svA);
                svB = fma2_(qv2[2*p + 1], kp.y, svB);
            }
            float2 sa = upk2(svA);
            float2 sb = upk2(svB);
            s[kk] += (sa.x + sa.y) + (sb.x + sb.y);
        }

        // tile max: 4 parallel chains (shallow serial depth)
        float x0 = s[0], x1 = s[1], x2 = s[2], x3 = s[3];
#pragma unroll
        for (int j = 4; j < 32; j += 4) {
            x0 = fmaxf(x0, s[j]);     x1 = fmaxf(x1, s[j + 1]);
            x2 = fmaxf(x2, s[j + 2]); x3 = fmaxf(x3, s[j + 3]);
        }
        float tmax = fmaxf(fmaxf(x0, x1), fmaxf(x2, x3));
        float mnew  = fmaxf(m, tmax);
        float alpha = exp2f(m - mnew);

        float p0 = 0.f, p1 = 0.f, p2 = 0.f, p3 = 0.f;
#pragma unroll
        for (int j = 0; j < 32; j += 4) {
            float e0 = exp2f(s[j]     - mnew);
            float e1 = exp2f(s[j + 1] - mnew);
            float e2 = exp2f(s[j + 2] - mnew);
            float e3 = exp2f(s[j + 3] - mnew);
            s[j] = e0; s[j + 1] = e1; s[j + 2] = e2; s[j + 3] = e3;
            p0 += e0; p1 += e1; p2 += e2; p3 += e3;
        }
        l = l * alpha + ((p0 + p1) + (p2 + p3));
        m = mnew;

        u64 al2 = pk2(alpha, alpha);
#pragma unroll
        for (int d = 0; d < 16; d++) o2[d] = mul2_(o2[d], al2);

#pragma unroll
        for (int kk = 0; kk < 32; kk++) {
            u64 p2k = pk2(s[kk], s[kk]);
            const ulonglong2* vr = reinterpret_cast<const ulonglong2*>(&Vs[cur][kk][0]);
#pragma unroll
            for (int p = 0; p < 8; p++) {
                ulonglong2 vp = vr[p];
                o2[2*p + 0] = fma2_(p2k, vp.x, o2[2*p + 0]);
                o2[2*p + 1] = fma2_(p2k, vp.y, o2[2*p + 1]);
            }
        }

        // stage next tile into the other buffer
        if (t < 31) {
            int nxt = 1 - cur;
            *reinterpret_cast<float4*>(&Ks[nxt][fr0][fc0]) = kf0;
            *reinterpret_cast<float4*>(&Ks[nxt][fr1][fc0]) = kf1;
            *reinterpret_cast<float4*>(&Vs[nxt][fr0][fc0]) = vf0;
            *reinterpret_cast<float4*>(&Vs[nxt][fr1][fc0]) = vf1;
        }
        __syncthreads();
    }

    float inv = 1.0f / l;
    float* ob = out + ((size_t)(b * N_ + qi)) * D_ + h * DK_;
#pragma unroll
    for (int d4 = 0; d4 < 8; d4++) {
        float2 t0 = upk2(o2[d4*2 + 0]);
        float2 t1 = upk2(o2[d4*2 + 1]);
        float4 t;
        t.x = t0.x * inv; t.y = t0.y * inv;
        t.z = t1.x * inv; t.w = t1.y * inv;
        *reinterpret_cast<float4*>(ob + d4 * 4) = t;
    }
}

// ---------------- LayerNorm over D=256 ----------------
__global__ void __launch_bounds__(256)
ln_kernel(const float* __restrict__ z,
          const float* __restrict__ g,
          const float* __restrict__ bta,
          float* __restrict__ out)
{
    int row = blockIdx.x;
    int t   = threadIdx.x;
    int lane = t & 31, wid = t >> 5;
    __shared__ float red1[8], red2[8];

    float vv = z[(size_t)row * 256 + t];
    float s = vv;
#pragma unroll
    for (int off = 16; off; off >>= 1) s += __shfl_xor_sync(0xffffffffu, s, off);
    if (lane == 0) red1[wid] = s;
    __syncthreads();
    float tot = 0.0f;
#pragma unroll
    for (int i = 0; i < 8; i++) tot += red1[i];
    float mu = tot * (1.0f / 256.0f);

    float d = vv - mu;
    float sq = d * d;
#pragma unroll
    for (int off = 16; off; off >>= 1) sq += __shfl_xor_sync(0xffffffffu, sq, off);
    if (lane == 0) red2[wid] = sq;
    __syncthreads();
    float var = 0.0f;
#pragma unroll
    for (int i = 0; i < 8; i++) var += red2[i];
    var *= (1.0f / 256.0f);

    out[(size_t)row * 256 + t] = d * rsqrtf(var + 1e-6f) * g[t] + bta[t];
}

// ---------------- launch ----------------
extern "C" void kernel_launch(void* const* d_in, const int* in_sizes, int n_in,
                              void* d_out, int out_size)
{
    (void)n_in; (void)out_size;

    const float *x, *svd_emb, *W_svd, *b_svd, *in_deg_emb, *out_deg_emb, *spatial_emb;
    const float *Wq, *Wk, *Wv, *Wa, *W1, *W2;
    const float *bq, *bk, *bv, *ba, *b1, *b2;
    const float *ln1_g, *ln1_b, *ln2_g, *ln2_b;
    const int *in_degrees, *out_degrees, *spatial_pos;

    if (in_sizes[1] == 1024) {
        // setup_inputs dict order
        x           = (const float*)d_in[0];
        in_degrees  = (const int*)  d_in[1];
        out_degrees = (const int*)  d_in[2];
        spatial_pos = (const int*)  d_in[3];
        svd_emb     = (const float*)d_in[4];
        in_deg_emb  = (const float*)d_in[5];
        out_deg_emb = (const float*)d_in[6];
        spatial_emb = (const float*)d_in[7];
        W_svd       = (const float*)d_in[8];
        b_svd       = (const float*)d_in[9];
        Wq = (const float*)d_in[10]; Wk = (const float*)d_in[11];
        Wv = (const float*)d_in[12]; Wa = (const float*)d_in[13];
        W1 = (const float*)d_in[14]; W2 = (const float*)d_in[15];
        bq = (const float*)d_in[16]; bk = (const float*)d_in[17];
        bv = (const float*)d_in[18]; ba = (const float*)d_in[19];
        b1 = (const float*)d_in[20]; b2 = (const float*)d_in[21];
        ln1_b = (const float*)d_in[22]; ln2_b = (const float*)d_in[23];
        ln1_g = (const float*)d_in[24]; ln2_g = (const float*)d_in[25];
    } else {
        // reference() signature order
        x           = (const float*)d_in[0];
        svd_emb     = (const float*)d_in[1];
        W_svd       = (const float*)d_in[2];
        b_svd       = (const float*)d_in[3];
        in_deg_emb  = (const float*)d_in[4];
        out_deg_emb = (const float*)d_in[5];
        spatial_emb = (const float*)d_in[6];
        Wq = (const float*)d_in[7];  bq = (const float*)d_in[8];
        Wk = (const float*)d_in[9];  bk = (const float*)d_in[10];
        Wv = (const float*)d_in[11]; bv = (const float*)d_in[12];
        Wa = (const float*)d_in[13]; ba = (const float*)d_in[14];
        ln1_g = (const float*)d_in[15]; ln1_b = (const float*)d_in[16];
        W1 = (const float*)d_in[17]; b1 = (const float*)d_in[18];
        W2 = (const float*)d_in[19]; b2 = (const float*)d_in[20];
        ln2_g = (const float*)d_in[21]; ln2_b = (const float*)d_in[22];
        in_degrees  = (const int*)d_in[23];
        out_degrees = (const int*)d_in[24];
        spatial_pos = (const int*)d_in[25];
    }

    float *hB, *qB, *kB, *vB, *t1B, *t2B, *nodeB, *biasB;
    cudaGetSymbolAddress((void**)&hB,    g_h);
    cudaGetSymbolAddress((void**)&qB,    g_q);
    cudaGetSymbolAddress((void**)&kB,    g_k);
    cudaGetSymbolAddress((void**)&vB,    g_v);
    cudaGetSymbolAddress((void**)&t1B,   g_t1);
    cudaGetSymbolAddress((void**)&t2B,   g_t2);
    cudaGetSymbolAddress((void**)&nodeB, g_node);
    cudaGetSymbolAddress((void**)&biasB, g_bias);

    float* outp = (float*)d_out;

    // prologue
    node_vec_kernel<<<N_, 256>>>(svd_emb, W_svd, b_svd, in_deg_emb, out_deg_emb,
                                 in_degrees, out_degrees, nodeB);
    add_node_kernel<<<BND / 256, 256>>>(x, nodeB, hB);
    bias_kernel<<<(N_ * N_) / 256, 256>>>(spatial_pos, spatial_emb, biasB);

    dim3 ggrid(B_ * N_ / GBM, D_ / GBN);       // (32, 4)
    dim3 qkvgrid(B_ * N_ / GBM, D_ / GBN, 3);  // (32, 4, 3)
    dim3 agrid(N_ / 128, B_ * H_);             // (8, 32)

    for (int l = 0; l < L_; l++) {
        const float* wq = Wq + (size_t)l * D_ * D_;
        const float* wk = Wk + (size_t)l * D_ * D_;
        const float* wv = Wv + (size_t)l * D_ * D_;
        const float* wa = Wa + (size_t)l * D_ * D_;
        const float* w1 = W1 + (size_t)l * D_ * D_;
        const float* w2 = W2 + (size_t)l * D_ * D_;

        qkv_kernel<<<qkvgrid, 256>>>(hB, wq, wk, wv,
                                     bq + l * D_, bk + l * D_, bv + l * D_,
                                     qB, kB, vB);

        attn_kernel<<<agrid, 128>>>(qB, kB, vB, biasB, t1B);

        gemm256_kernel<<<ggrid, 256>>>(t1B, wa, ba + l * D_, hB, t2B, 0);
        ln_kernel<<<B_ * N_, 256>>>(t2B, ln1_g + l * D_, ln1_b + l * D_, hB);

        gemm256_kernel<<<ggrid, 256>>>(hB, w1, b1 + l * D_, nullptr, t1B, 1);
        gemm256_kernel<<<ggrid, 256>>>(t1B, w2, b2 + l * D_, hB, t2B, 0);

        float* ln2_dst = (l == L_ - 1) ? outp : hB;
        ln_kernel<<<B_ * N_, 256>>>(t2B, ln2_g + l * D_, ln2_b + l * D_, ln2_dst);
    }
}